// round 10
// baseline (speedup 1.0000x reference)
#include <cuda_runtime.h>
#include <cuda_fp16.h>
#include <cstdint>

// Problem constants (fixed by setup_inputs)
#define BWIN   4096
#define NTOK   49
#define CDIM   256
#define NHEAD  8
#define MROWS  (BWIN * NTOK)   // 200704

// ---------------------------------------------------------------------------
// Scratch (device globals; no runtime allocation allowed)
// ---------------------------------------------------------------------------
__device__ __half   g_qkv[(size_t)MROWS * 768];
__device__ __half   g_att[(size_t)MROWS * CDIM];
__device__ uint32_t g_wqkv[6 * 16 * 32 * 32];        // qkv_w frag-major fp16 words
__device__ uint32_t g_wproj[2 * 16 * 32 * 32];       // proj_w frag-major fp16 words
__device__ uint32_t g_bias[NHEAD * 64 * 32];         // [h][i][t][8] half2 words

__device__ __forceinline__ uint32_t pack_h2(float a, float b) {
    __half2 h = __floats2half2_rn(a, b);
    return *(uint32_t*)&h;
}

// ---------------------------------------------------------------------------
// Weight conversion: fp32 W[K,N] row-major -> fp16 fragment-major words.
//   idx = ((nblk*16 + kc)*32 + (nt*2+reg))*32 + lane, lane = g*4+t
//   n = nblk*128 + nt*8 + g;  k = kc*16 + reg*8 + t*2
//   word = half2(w[k][n], w[k+1][n])
// ---------------------------------------------------------------------------
__global__ void convert_w(const float* __restrict__ w, uint32_t* __restrict__ dst, int N)
{
    const int idx  = blockIdx.x * 256 + threadIdx.x;
    const int lane = idx & 31;
    const int row  = (idx >> 5) & 31;
    const int kc   = (idx >> 10) & 15;
    const int nblk = idx >> 14;
    const int nt = row >> 1, reg = row & 1;
    const int g = lane >> 2, t = lane & 3;
    const int n = nblk * 128 + nt * 8 + g;
    const int k = kc * 16 + reg * 8 + t * 2;
    dst[idx] = pack_h2(w[(size_t)k * N + n], w[(size_t)(k + 1) * N + n]);
}

// ---------------------------------------------------------------------------
// Bias+mask table: g_bias[((h*64+i)*4 + t)*8 + nt] = half2(B(i,j), B(i,j+1)),
// j = nt*8 + 2t; invalid -> -10000. uint4-loadable per (i,t).
// ---------------------------------------------------------------------------
__global__ void build_bias(const float* __restrict__ rpb, uint32_t* __restrict__ dst)
{
    const int idx = blockIdx.x * 256 + threadIdx.x;   // 0..16383
    const int nt = idx & 7;
    const int t  = (idx >> 3) & 3;
    const int i  = (idx >> 5) & 63;
    const int h  = idx >> 11;
    const int j0 = nt * 8 + 2 * t;
    float v[2];
#pragma unroll
    for (int e = 0; e < 2; e++) {
        const int j = j0 + e;
        if (i < NTOK && j < NTOK && nt < 7) {
            const int xi = i / 7, yi = i - xi * 7;
            const int xj = j / 7, yj = j - xj * 7;
            v[e] = rpb[((xi - xj + 6) * 13 + (yi - yj + 6)) * 8 + h];
        } else {
            v[e] = -10000.0f;
        }
    }
    dst[idx] = pack_h2(v[0], v[1]);
}

// ---------------------------------------------------------------------------
// A-resident fp16 tensor-core GEMM, BM=256: C[M,N] = A[M,256] @ W[256,N] + b.
// One CTA = 256 rows x full N (loop over N/128 blocks), 256 threads (8 warps,
// warp tile 64x64: wm = warp&3, wn = warp>>2).
// A converted once into 128KB smem fragment image; B consumed preconverted
// frag-major (1 uint4 per thread per k-iter), double-buffered, prefetch 2.
// L1 wavefronts/mma drop 1.5 -> 1.25 vs BM=128 (B fill amortized over 2x M).
// ---------------------------------------------------------------------------
template<typename TA, typename TC, int N>
__global__ __launch_bounds__(256, 1)
void h16_gemm(const TA* __restrict__ A, const uint32_t* __restrict__ Bw,
              const float* __restrict__ bias, TC* __restrict__ C)
{
    constexpr int K = 256, BK = 16, NT = K / BK, NBLK = N / 128;
    extern __shared__ uint32_t smem[];
    uint32_t* Asm = smem;                 // 16 kc * 16 mt * 4 reg * 32 = 32768 words
    uint32_t* Bsm = smem + 32768;         // 2 buffers x 1024 words

    const int tid  = threadIdx.x;
    const int lane = tid & 31;
    const int warp = tid >> 5;
    const int wm   = warp & 3;            // m quarter (0..3)
    const int wn   = warp >> 2;           // n half (0..1)
    const int bm   = blockIdx.x * 256;

    // ---- A resident fill (once): fragment image for all 16 k-chunks --------
    if constexpr (sizeof(TA) == 4) {
#pragma unroll
        for (int it = 0; it < 64; it++) {
            const int e = it * 256 + tid;            // (row, c4)
            const int row = e >> 6, c4 = e & 63;
            const int k = c4 * 4;
            const int kc = k >> 4;
            const int reg = ((row >> 3) & 1) + ((k >> 3) & 1) * 2;
            const int t0 = (k & 7) >> 1;             // 0 or 2
            const int mt = row >> 4, g = row & 7;
            float4 v = *(const float4*)((const float*)A + (size_t)(bm + row) * K + k);
            uint2 w;
            w.x = pack_h2(v.x, v.y);
            w.y = pack_h2(v.z, v.w);
            *(uint2*)&Asm[((kc * 16 + mt) * 4 + reg) * 32 + g * 4 + t0] = w;
        }
    } else {
#pragma unroll
        for (int it = 0; it < 32; it++) {
            const int e = it * 256 + tid;            // (row, c8)
            const int row = e >> 5, c8 = e & 31;
            const int k = c8 * 8;                    // k%8 == 0 -> t0 = 0
            const int kc = k >> 4;
            const int reg = ((row >> 3) & 1) + ((k >> 3) & 1) * 2;
            const int mt = row >> 4, g = row & 7;
            uint4 v = *(const uint4*)((const __half*)A + (size_t)(bm + row) * K + k);
            *(uint4*)&Asm[((kc * 16 + mt) * 4 + reg) * 32 + g * 4] = v;
        }
    }

    uint4 stage[2];
    auto loadB = [&](int s, int kc, const uint32_t* bw) {
        stage[s] = ((const uint4*)(bw + kc * 1024))[tid];
    };
    auto stsB = [&](int buf, int s) {
        ((uint4*)(Bsm + buf * 1024))[tid] = stage[s];
    };

    float acc[4][8][4];

    auto compute = [&](int buf, int kc) {
        uint32_t af[4][4];
#pragma unroll
        for (int mt = 0; mt < 4; mt++) {
            const int base = ((kc * 16 + wm * 4 + mt) * 4) * 32 + lane;
#pragma unroll
            for (int r = 0; r < 4; r++) af[mt][r] = Asm[base + r * 32];
        }
        uint32_t bf[8][2];
        const uint32_t* bp = Bsm + buf * 1024;
#pragma unroll
        for (int nt = 0; nt < 8; nt++) {
            bf[nt][0] = bp[((wn * 8 + nt) * 2 + 0) * 32 + lane];
            bf[nt][1] = bp[((wn * 8 + nt) * 2 + 1) * 32 + lane];
        }
#pragma unroll
        for (int mt = 0; mt < 4; mt++) {
#pragma unroll
            for (int nt = 0; nt < 8; nt++) {
                asm volatile(
                    "mma.sync.aligned.m16n8k16.row.col.f32.f16.f16.f32 "
                    "{%0,%1,%2,%3}, {%4,%5,%6,%7}, {%8,%9}, {%0,%1,%2,%3};"
                    : "+f"(acc[mt][nt][0]), "+f"(acc[mt][nt][1]),
                      "+f"(acc[mt][nt][2]), "+f"(acc[mt][nt][3])
                    : "r"(af[mt][0]), "r"(af[mt][1]), "r"(af[mt][2]), "r"(af[mt][3]),
                      "r"(bf[nt][0]), "r"(bf[nt][1]));
            }
        }
    };

    for (int nblk = 0; nblk < NBLK; nblk++) {
        const uint32_t* bw = Bw + (size_t)nblk * NT * 1024;
#pragma unroll
        for (int i = 0; i < 4; i++)
#pragma unroll
            for (int j = 0; j < 8; j++)
#pragma unroll
                for (int r = 0; r < 4; r++) acc[i][j][r] = 0.f;

        loadB(0, 0, bw);
        loadB(1, 1, bw);
        stsB(0, 0);
        __syncthreads();

        int buf = 0;
#pragma unroll 2
        for (int t = 0; t < NT; t++) {
            if (t + 2 < NT) loadB(t & 1, t + 2, bw);
            compute(buf, t);
            if (t + 1 < NT) stsB(buf ^ 1, (t + 1) & 1);
            __syncthreads();
            buf ^= 1;
        }

        // epilogue: bias + store
        const int g = lane >> 2, tig = lane & 3;
#pragma unroll
        for (int mt = 0; mt < 4; mt++) {
            const int r0 = bm + wm * 64 + mt * 16 + g;
#pragma unroll
            for (int nt = 0; nt < 8; nt++) {
                const int col = nblk * 128 + wn * 64 + nt * 8 + tig * 2;
                const float b0 = __ldg(bias + col);
                const float b1 = __ldg(bias + col + 1);
                if constexpr (sizeof(TC) == 2) {
                    __half* cp = (__half*)C;
                    *(__half2*)(cp + (size_t)r0 * N + col) =
                        __floats2half2_rn(acc[mt][nt][0] + b0, acc[mt][nt][1] + b1);
                    *(__half2*)(cp + (size_t)(r0 + 8) * N + col) =
                        __floats2half2_rn(acc[mt][nt][2] + b0, acc[mt][nt][3] + b1);
                } else {
                    float* cp = (float*)C;
                    *(float2*)(cp + (size_t)r0 * N + col) =
                        make_float2(acc[mt][nt][0] + b0, acc[mt][nt][1] + b1);
                    *(float2*)(cp + (size_t)(r0 + 8) * N + col) =
                        make_float2(acc[mt][nt][2] + b0, acc[mt][nt][3] + b1);
                }
            }
        }
    }
}

// ---------------------------------------------------------------------------
// PURE fp16 tensor-core windowed attention (mma.sync), vectorized bias table.
// ---------------------------------------------------------------------------
__global__ __launch_bounds__(128)
void window_attn_h16(const __half* __restrict__ qkv,
                     const uint32_t* __restrict__ biasT,
                     __half* __restrict__ out)
{
    __shared__ uint32_t sq [64 * 36];
    __shared__ uint32_t sk [56 * 36];
    __shared__ uint32_t svT[32 * 36];
    __shared__ uint32_t sp [64 * 36];

    const int b = blockIdx.x;
    const int h = blockIdx.y;
    const int tid  = threadIdx.x;
    const int lane = tid & 31;
    const int warp = tid >> 5;
    const int g = lane >> 2;
    const int t = lane & 3;

    const float scale = 0.17677669529663687f;
    const __half* base = qkv + (size_t)b * NTOK * 768 + h * 32;

#pragma unroll
    for (int it = 0; it < 2; it++) {
        const int e = tid + it * 128;
        const int row = e >> 2, c = e & 3;
        const int sr = row < NTOK ? row : NTOK - 1;
        *(uint4*)&sq[row * 36 + c * 4] =
            *(const uint4*)(base + (size_t)sr * 768 + c * 8);
    }
#pragma unroll
    for (int it = 0; it < 2; it++) {
        const int e = tid + it * 128;
        if (e < 224) {
            const int row = e >> 2, c = e & 3;
            const int sr = row < NTOK ? row : NTOK - 1;
            *(uint4*)&sk[row * 36 + c * 4] =
                *(const uint4*)(base + (size_t)sr * 768 + 256 + c * 8);
        }
    }
    if (tid < 112) {
        const int tp = tid >> 2, dg = tid & 3;
        int t0 = 2 * tp, t1 = 2 * tp + 1;
        if (t0 > NTOK - 1) t0 = NTOK - 1;
        if (t1 > NTOK - 1) t1 = NTOK - 1;
        uint4 r0 = *(const uint4*)(base + (size_t)t0 * 768 + 512 + dg * 8);
        uint4 r1 = *(const uint4*)(base + (size_t)t1 * 768 + 512 + dg * 8);
        const __half* h0 = (const __half*)&r0;
        const __half* h1 = (const __half*)&r1;
#pragma unroll
        for (int i = 0; i < 8; i++) {
            __half2 w = __halves2half2(h0[i], h1[i]);
            svT[(dg * 8 + i) * 36 + tp] = *(uint32_t*)&w;
        }
    }
#pragma unroll
    for (int it = 0; it < 2; it++) {
        const int e = tid + it * 128;
        sp[(e >> 2) * 36 + 28 + (e & 3)] = 0;
    }
    svT[(tid >> 2) * 36 + 28 + (tid & 3)] = 0;
    __syncthreads();

    const int mtb = warp * 16;
    float sc[7][4];
#pragma unroll
    for (int nt = 0; nt < 7; nt++)
#pragma unroll
        for (int r = 0; r < 4; r++) sc[nt][r] = 0.f;

#pragma unroll
    for (int ko = 0; ko < 2; ko++) {
        const uint32_t a0 = sq[(mtb + g) * 36 + ko * 8 + t];
        const uint32_t a1 = sq[(mtb + g + 8) * 36 + ko * 8 + t];
        const uint32_t a2 = sq[(mtb + g) * 36 + ko * 8 + 4 + t];
        const uint32_t a3 = sq[(mtb + g + 8) * 36 + ko * 8 + 4 + t];
#pragma unroll
        for (int nt = 0; nt < 7; nt++) {
            const uint32_t b0 = sk[(nt * 8 + g) * 36 + ko * 8 + t];
            const uint32_t b1 = sk[(nt * 8 + g) * 36 + ko * 8 + 4 + t];
            asm volatile(
                "mma.sync.aligned.m16n8k16.row.col.f32.f16.f16.f32 "
                "{%0,%1,%2,%3}, {%4,%5,%6,%7}, {%8,%9}, {%0,%1,%2,%3};"
                : "+f"(sc[nt][0]), "+f"(sc[nt][1]), "+f"(sc[nt][2]), "+f"(sc[nt][3])
                : "r"(a0), "r"(a1), "r"(a2), "r"(a3), "r"(b0), "r"(b1));
        }
    }

    const int i0 = mtb + g, i1 = i0 + 8;
    const uint4* bp0 = (const uint4*)biasT + (((h * 64 + i0) * 4 + t) * 2);
    const uint4* bp1 = (const uint4*)biasT + (((h * 64 + i1) * 4 + t) * 2);
    uint4 wa0 = __ldg(bp0), wb0 = __ldg(bp0 + 1);
    uint4 wa1 = __ldg(bp1), wb1 = __ldg(bp1 + 1);
    const uint32_t bw0[8] = {wa0.x, wa0.y, wa0.z, wa0.w, wb0.x, wb0.y, wb0.z, wb0.w};
    const uint32_t bw1[8] = {wa1.x, wa1.y, wa1.z, wa1.w, wb1.x, wb1.y, wb1.z, wb1.w};

    float m0 = -1e30f, m1 = -1e30f;
#pragma unroll
    for (int nt = 0; nt < 7; nt++) {
        const float2 f0 = __half22float2(*(const __half2*)&bw0[nt]);
        const float2 f1 = __half22float2(*(const __half2*)&bw1[nt]);
        sc[nt][0] = fmaf(sc[nt][0], scale, f0.x);
        sc[nt][1] = fmaf(sc[nt][1], scale, f0.y);
        sc[nt][2] = fmaf(sc[nt][2], scale, f1.x);
        sc[nt][3] = fmaf(sc[nt][3], scale, f1.y);
        m0 = fmaxf(m0, fmaxf(sc[nt][0], sc[nt][1]));
        m1 = fmaxf(m1, fmaxf(sc[nt][2], sc[nt][3]));
    }
    m0 = fmaxf(m0, __shfl_xor_sync(0xffffffffu, m0, 1));
    m0 = fmaxf(m0, __shfl_xor_sync(0xffffffffu, m0, 2));
    m1 = fmaxf(m1, __shfl_xor_sync(0xffffffffu, m1, 1));
    m1 = fmaxf(m1, __shfl_xor_sync(0xffffffffu, m1, 2));

    float s0 = 0.f, s1 = 0.f;
#pragma unroll
    for (int nt = 0; nt < 7; nt++) {
        float p0 = __expf(sc[nt][0] - m0);
        float p1 = __expf(sc[nt][1] - m0);
        float p2 = __expf(sc[nt][2] - m1);
        float p3 = __expf(sc[nt][3] - m1);
        sc[nt][0] = p0; sc[nt][1] = p1; sc[nt][2] = p2; sc[nt][3] = p3;
        s0 += p0 + p1;
        s1 += p2 + p3;
    }
    s0 += __shfl_xor_sync(0xffffffffu, s0, 1);
    s0 += __shfl_xor_sync(0xffffffffu, s0, 2);
    s1 += __shfl_xor_sync(0xffffffffu, s1, 1);
    s1 += __shfl_xor_sync(0xffffffffu, s1, 2);
    const float inv0 = 1.f / s0, inv1 = 1.f / s1;

#pragma unroll
    for (int nt = 0; nt < 7; nt++) {
        sp[i0 * 36 + nt * 4 + t] = pack_h2(sc[nt][0], sc[nt][1]);
        sp[i1 * 36 + nt * 4 + t] = pack_h2(sc[nt][2], sc[nt][3]);
    }
    __syncwarp();

    float ov[4][4];
#pragma unroll
    for (int nt = 0; nt < 4; nt++)
#pragma unroll
        for (int r = 0; r < 4; r++) ov[nt][r] = 0.f;

#pragma unroll
    for (int ko = 0; ko < 4; ko++) {
        const uint32_t a0 = sp[(mtb + g) * 36 + ko * 8 + t];
        const uint32_t a1 = sp[(mtb + g + 8) * 36 + ko * 8 + t];
        const uint32_t a2 = sp[(mtb + g) * 36 + ko * 8 + 4 + t];
        const uint32_t a3 = sp[(mtb + g + 8) * 36 + ko * 8 + 4 + t];
#pragma unroll
        for (int nt = 0; nt < 4; nt++) {
            const uint32_t b0 = svT[(nt * 8 + g) * 36 + ko * 8 + t];
            const uint32_t b1 = svT[(nt * 8 + g) * 36 + ko * 8 + 4 + t];
            asm volatile(
                "mma.sync.aligned.m16n8k16.row.col.f32.f16.f16.f32 "
                "{%0,%1,%2,%3}, {%4,%5,%6,%7}, {%8,%9}, {%0,%1,%2,%3};"
                : "+f"(ov[nt][0]), "+f"(ov[nt][1]), "+f"(ov[nt][2]), "+f"(ov[nt][3])
                : "r"(a0), "r"(a1), "r"(a2), "r"(a3), "r"(b0), "r"(b1));
        }
    }

    const bool v0 = i0 < NTOK, v1 = i1 < NTOK;
#pragma unroll
    for (int nt = 0; nt < 4; nt++) {
        const int col = h * 32 + nt * 8 + 2 * t;
        if (v0) {
            *(__half2*)(out + ((size_t)b * NTOK + i0) * CDIM + col) =
                __floats2half2_rn(ov[nt][0] * inv0, ov[nt][1] * inv0);
        }
        if (v1) {
            *(__half2*)(out + ((size_t)b * NTOK + i1) * CDIM + col) =
                __floats2half2_rn(ov[nt][2] * inv1, ov[nt][3] * inv1);
        }
    }
}

// ---------------------------------------------------------------------------
// Launch
// ---------------------------------------------------------------------------
extern "C" void kernel_launch(void* const* d_in, const int* in_sizes, int n_in,
                              void* d_out, int out_size)
{
    const float* x      = (const float*)d_in[0];
    const float* qkv_w  = (const float*)d_in[1];
    const float* qkv_b  = (const float*)d_in[2];
    const float* rpb    = (const float*)d_in[3];
    const float* proj_w = (const float*)d_in[4];
    const float* proj_b = (const float*)d_in[5];
    float* out = (float*)d_out;

    __half* qkvh = nullptr;
    __half* atth = nullptr;
    uint32_t* wqkv = nullptr;
    uint32_t* wproj = nullptr;
    uint32_t* biasT = nullptr;
    cudaGetSymbolAddress((void**)&qkvh, g_qkv);
    cudaGetSymbolAddress((void**)&atth, g_att);
    cudaGetSymbolAddress((void**)&wqkv, g_wqkv);
    cudaGetSymbolAddress((void**)&wproj, g_wproj);
    cudaGetSymbolAddress((void**)&biasT, g_bias);

    constexpr int SMEM = (32768 + 2 * 1024) * 4;   // 139264 B
    cudaFuncSetAttribute(h16_gemm<float, __half, 768>,
                         cudaFuncAttributeMaxDynamicSharedMemorySize, SMEM);
    cudaFuncSetAttribute(h16_gemm<__half, float, 256>,
                         cudaFuncAttributeMaxDynamicSharedMemorySize, SMEM);

    // 0) one-time conversions (tiny)
    convert_w<<<384, 256>>>(qkv_w, wqkv, 768);
    convert_w<<<128, 256>>>(proj_w, wproj, 256);
    build_bias<<<64, 256>>>(rpb, biasT);

    // 1) QKV GEMM (A-resident BM=256, fp16 out)
    h16_gemm<float, __half, 768><<<MROWS / 256, 256, SMEM>>>(x, wqkv, qkv_b, qkvh);

    // 2) Windowed attention (pure fp16 tensor cores, vectorized bias)
    {
        dim3 grid(BWIN, NHEAD);
        window_attn_h16<<<grid, 128>>>(qkvh, biasT, atth);
    }

    // 3) Projection GEMM (A-resident BM=256, fp32 out)
    h16_gemm<__half, float, 256><<<MROWS / 256, 256, SMEM>>>(atth, wproj, proj_b, out);
}

// round 11
// speedup vs baseline: 1.2280x; 1.2280x over previous
#include <cuda_runtime.h>
#include <cuda_fp16.h>
#include <cstdint>

// Problem constants (fixed by setup_inputs)
#define BWIN   4096
#define NTOK   49
#define CDIM   256
#define NHEAD  8
#define MROWS  (BWIN * NTOK)   // 200704

// ---------------------------------------------------------------------------
// Scratch (device globals; no runtime allocation allowed)
// ---------------------------------------------------------------------------
__device__ __half   g_qkv[(size_t)MROWS * 768];
__device__ __half   g_att[(size_t)MROWS * CDIM];
__device__ uint32_t g_wqkv[6 * 16 * 32 * 32];        // qkv_w frag-major fp16 words
__device__ uint32_t g_wproj[2 * 16 * 32 * 32];       // proj_w frag-major fp16 words
__device__ uint32_t g_bias[NHEAD * 64 * 32];         // [h][i][t][8] half2 words

__device__ __forceinline__ uint32_t pack_h2(float a, float b) {
    __half2 h = __floats2half2_rn(a, b);
    return *(uint32_t*)&h;
}

// ---------------------------------------------------------------------------
// Weight conversion: fp32 W[K,N] row-major -> fp16 fragment-major words.
//   idx = ((nblk*16 + kc)*32 + (nt*2+reg))*32 + lane, lane = g*4+t
//   n = nblk*128 + nt*8 + g;  k = kc*16 + reg*8 + t*2
//   word = half2(w[k][n], w[k+1][n])
// ---------------------------------------------------------------------------
__global__ void convert_w(const float* __restrict__ w, uint32_t* __restrict__ dst, int N)
{
    const int idx  = blockIdx.x * 256 + threadIdx.x;
    const int lane = idx & 31;
    const int row  = (idx >> 5) & 31;
    const int kc   = (idx >> 10) & 15;
    const int nblk = idx >> 14;
    const int nt = row >> 1, reg = row & 1;
    const int g = lane >> 2, t = lane & 3;
    const int n = nblk * 128 + nt * 8 + g;
    const int k = kc * 16 + reg * 8 + t * 2;
    dst[idx] = pack_h2(w[(size_t)k * N + n], w[(size_t)(k + 1) * N + n]);
}

// ---------------------------------------------------------------------------
// Bias+mask table: g_bias[((h*64+i)*4 + t)*8 + nt] = half2(B(i,j), B(i,j+1)),
// j = nt*8 + 2t; invalid -> -10000. uint4-loadable per (i,t).
// ---------------------------------------------------------------------------
__global__ void build_bias(const float* __restrict__ rpb, uint32_t* __restrict__ dst)
{
    const int idx = blockIdx.x * 256 + threadIdx.x;   // 0..16383
    const int nt = idx & 7;
    const int t  = (idx >> 3) & 3;
    const int i  = (idx >> 5) & 63;
    const int h  = idx >> 11;
    const int j0 = nt * 8 + 2 * t;
    float v[2];
#pragma unroll
    for (int e = 0; e < 2; e++) {
        const int j = j0 + e;
        if (i < NTOK && j < NTOK && nt < 7) {
            const int xi = i / 7, yi = i - xi * 7;
            const int xj = j / 7, yj = j - xj * 7;
            v[e] = rpb[((xi - xj + 6) * 13 + (yi - yj + 6)) * 8 + h];
        } else {
            v[e] = -10000.0f;
        }
    }
    dst[idx] = pack_h2(v[0], v[1]);
}

// ---------------------------------------------------------------------------
// BARRIER-FREE A-resident fp16 tensor-core GEMM (BM=128, 4 warps, 2 CTA/SM).
// A converted once into a 64KB smem fragment image (one sync). B fragments
// are loaded DIRECTLY from gmem (preconverted frag-major; each frag word
// access is a 128B-coalesced LDG.32 hitting L1/L2). The k-loop has NO
// __syncthreads, no STS, no staging: the scoreboard pipelines LDG/LDS/HMMA
// freely across the fully unrolled 16 k-chunks.
// ---------------------------------------------------------------------------
template<typename TA, typename TC, int N>
__global__ __launch_bounds__(128, 2)
void h16_gemm(const TA* __restrict__ A, const uint32_t* __restrict__ Bw,
              const float* __restrict__ bias, TC* __restrict__ C)
{
    constexpr int K = 256, NT = 16, NBLK = N / 128;
    extern __shared__ uint32_t Asm[];     // 16 kc * 8 mt * 4 reg * 32 = 16384 words

    const int tid  = threadIdx.x;
    const int lane = tid & 31;
    const int warp = tid >> 5;
    const int wm   = warp & 1;
    const int wn   = warp >> 1;
    const int bm   = blockIdx.x * 128;

    // ---- A resident fill (once) ---------------------------------------------
    if constexpr (sizeof(TA) == 4) {
#pragma unroll
        for (int it = 0; it < 32; it++) {
            const int e = it * 128 + tid;            // (row, c4)
            const int row = e >> 5, c4 = e & 31;     // 128 rows x 32 float4... no:
            // 128 rows x 64 cols -> rows = e>>6? K=256 floats -> 64 float4/row
            // redo: 128*64 float4 = 8192 loads, 128 thr -> 64 iters
        }
        // (see loop below)
#pragma unroll
        for (int it = 0; it < 64; it++) {
            const int e = it * 128 + tid;
            const int row = e >> 6, c4 = e & 63;
            const int k = c4 * 4;
            const int kc = k >> 4;
            const int reg = ((row >> 3) & 1) + ((k >> 3) & 1) * 2;
            const int t0 = (k & 7) >> 1;
            const int mt = (row >> 4);
            const int g = row & 7;
            float4 v = *(const float4*)((const float*)A + (size_t)(bm + row) * K + k);
            uint2 w;
            w.x = pack_h2(v.x, v.y);
            w.y = pack_h2(v.z, v.w);
            *(uint2*)&Asm[((kc * 8 + mt) * 4 + reg) * 32 + g * 4 + t0] = w;
        }
    } else {
#pragma unroll
        for (int it = 0; it < 32; it++) {
            const int e = it * 128 + tid;
            const int row = e >> 5, c8 = e & 31;
            const int k = c8 * 8;
            const int kc = k >> 4;
            const int reg = ((row >> 3) & 1) + ((k >> 3) & 1) * 2;
            const int mt = (row >> 4);
            const int g = row & 7;
            uint4 v = *(const uint4*)((const __half*)A + (size_t)(bm + row) * K + k);
            *(uint4*)&Asm[((kc * 8 + mt) * 4 + reg) * 32 + g * 4] = v;
        }
    }
    __syncthreads();    // the ONLY block-wide barrier

    float acc[4][8][4];

    for (int nblk = 0; nblk < NBLK; nblk++) {
#pragma unroll
        for (int i = 0; i < 4; i++)
#pragma unroll
            for (int j = 0; j < 8; j++)
#pragma unroll
                for (int r = 0; r < 4; r++) acc[i][j][r] = 0.f;

        const uint32_t* bw = Bw + ((size_t)nblk * 16) * 1024
                           + ((wn * 8) * 2) * 32 + lane;

#pragma unroll
        for (int kc = 0; kc < NT; kc++) {
            // B fragments straight from gmem (coalesced, L1/L2-resident)
            uint32_t bf[8][2];
            const uint32_t* bk = bw + kc * 1024;
#pragma unroll
            for (int nt = 0; nt < 8; nt++) {
                bf[nt][0] = __ldg(bk + (nt * 2 + 0) * 32);
                bf[nt][1] = __ldg(bk + (nt * 2 + 1) * 32);
            }
            // A fragments from resident smem
            uint32_t af[4][4];
#pragma unroll
            for (int mt = 0; mt < 4; mt++) {
                const int base = ((kc * 8 + wm * 4 + mt) * 4) * 32 + lane;
#pragma unroll
                for (int r = 0; r < 4; r++) af[mt][r] = Asm[base + r * 32];
            }
#pragma unroll
            for (int mt = 0; mt < 4; mt++) {
#pragma unroll
                for (int nt = 0; nt < 8; nt++) {
                    asm volatile(
                        "mma.sync.aligned.m16n8k16.row.col.f32.f16.f16.f32 "
                        "{%0,%1,%2,%3}, {%4,%5,%6,%7}, {%8,%9}, {%0,%1,%2,%3};"
                        : "+f"(acc[mt][nt][0]), "+f"(acc[mt][nt][1]),
                          "+f"(acc[mt][nt][2]), "+f"(acc[mt][nt][3])
                        : "r"(af[mt][0]), "r"(af[mt][1]), "r"(af[mt][2]), "r"(af[mt][3]),
                          "r"(bf[nt][0]), "r"(bf[nt][1]));
                }
            }
        }

        // epilogue: bias + store (no sync needed; acc in regs)
        const int g = lane >> 2, tig = lane & 3;
#pragma unroll
        for (int mt = 0; mt < 4; mt++) {
            const int r0 = bm + wm * 64 + mt * 16 + g;
#pragma unroll
            for (int nt = 0; nt < 8; nt++) {
                const int col = nblk * 128 + wn * 64 + nt * 8 + tig * 2;
                const float b0 = __ldg(bias + col);
                const float b1 = __ldg(bias + col + 1);
                if constexpr (sizeof(TC) == 2) {
                    __half* cp = (__half*)C;
                    *(__half2*)(cp + (size_t)r0 * N + col) =
                        __floats2half2_rn(acc[mt][nt][0] + b0, acc[mt][nt][1] + b1);
                    *(__half2*)(cp + (size_t)(r0 + 8) * N + col) =
                        __floats2half2_rn(acc[mt][nt][2] + b0, acc[mt][nt][3] + b1);
                } else {
                    float* cp = (float*)C;
                    *(float2*)(cp + (size_t)r0 * N + col) =
                        make_float2(acc[mt][nt][0] + b0, acc[mt][nt][1] + b1);
                    *(float2*)(cp + (size_t)(r0 + 8) * N + col) =
                        make_float2(acc[mt][nt][2] + b0, acc[mt][nt][3] + b1);
                }
            }
        }
    }
}

// ---------------------------------------------------------------------------
// PURE fp16 tensor-core windowed attention (mma.sync), vectorized bias table.
// (unchanged from round 10)
// ---------------------------------------------------------------------------
__global__ __launch_bounds__(128)
void window_attn_h16(const __half* __restrict__ qkv,
                     const uint32_t* __restrict__ biasT,
                     __half* __restrict__ out)
{
    __shared__ uint32_t sq [64 * 36];
    __shared__ uint32_t sk [56 * 36];
    __shared__ uint32_t svT[32 * 36];
    __shared__ uint32_t sp [64 * 36];

    const int b = blockIdx.x;
    const int h = blockIdx.y;
    const int tid  = threadIdx.x;
    const int lane = tid & 31;
    const int warp = tid >> 5;
    const int g = lane >> 2;
    const int t = lane & 3;

    const float scale = 0.17677669529663687f;
    const __half* base = qkv + (size_t)b * NTOK * 768 + h * 32;

#pragma unroll
    for (int it = 0; it < 2; it++) {
        const int e = tid + it * 128;
        const int row = e >> 2, c = e & 3;
        const int sr = row < NTOK ? row : NTOK - 1;
        *(uint4*)&sq[row * 36 + c * 4] =
            *(const uint4*)(base + (size_t)sr * 768 + c * 8);
    }
#pragma unroll
    for (int it = 0; it < 2; it++) {
        const int e = tid + it * 128;
        if (e < 224) {
            const int row = e >> 2, c = e & 3;
            const int sr = row < NTOK ? row : NTOK - 1;
            *(uint4*)&sk[row * 36 + c * 4] =
                *(const uint4*)(base + (size_t)sr * 768 + 256 + c * 8);
        }
    }
    if (tid < 112) {
        const int tp = tid >> 2, dg = tid & 3;
        int t0 = 2 * tp, t1 = 2 * tp + 1;
        if (t0 > NTOK - 1) t0 = NTOK - 1;
        if (t1 > NTOK - 1) t1 = NTOK - 1;
        uint4 r0 = *(const uint4*)(base + (size_t)t0 * 768 + 512 + dg * 8);
        uint4 r1 = *(const uint4*)(base + (size_t)t1 * 768 + 512 + dg * 8);
        const __half* h0 = (const __half*)&r0;
        const __half* h1 = (const __half*)&r1;
#pragma unroll
        for (int i = 0; i < 8; i++) {
            __half2 w = __halves2half2(h0[i], h1[i]);
            svT[(dg * 8 + i) * 36 + tp] = *(uint32_t*)&w;
        }
    }
#pragma unroll
    for (int it = 0; it < 2; it++) {
        const int e = tid + it * 128;
        sp[(e >> 2) * 36 + 28 + (e & 3)] = 0;
    }
    svT[(tid >> 2) * 36 + 28 + (tid & 3)] = 0;
    __syncthreads();

    const int mtb = warp * 16;
    float sc[7][4];
#pragma unroll
    for (int nt = 0; nt < 7; nt++)
#pragma unroll
        for (int r = 0; r < 4; r++) sc[nt][r] = 0.f;

#pragma unroll
    for (int ko = 0; ko < 2; ko++) {
        const uint32_t a0 = sq[(mtb + g) * 36 + ko * 8 + t];
        const uint32_t a1 = sq[(mtb + g + 8) * 36 + ko * 8 + t];
        const uint32_t a2 = sq[(mtb + g) * 36 + ko * 8 + 4 + t];
        const uint32_t a3 = sq[(mtb + g + 8) * 36 + ko * 8 + 4 + t];
#pragma unroll
        for (int nt = 0; nt < 7; nt++) {
            const uint32_t b0 = sk[(nt * 8 + g) * 36 + ko * 8 + t];
            const uint32_t b1 = sk[(nt * 8 + g) * 36 + ko * 8 + 4 + t];
            asm volatile(
                "mma.sync.aligned.m16n8k16.row.col.f32.f16.f16.f32 "
                "{%0,%1,%2,%3}, {%4,%5,%6,%7}, {%8,%9}, {%0,%1,%2,%3};"
                : "+f"(sc[nt][0]), "+f"(sc[nt][1]), "+f"(sc[nt][2]), "+f"(sc[nt][3])
                : "r"(a0), "r"(a1), "r"(a2), "r"(a3), "r"(b0), "r"(b1));
        }
    }

    const int i0 = mtb + g, i1 = i0 + 8;
    const uint4* bp0 = (const uint4*)biasT + (((h * 64 + i0) * 4 + t) * 2);
    const uint4* bp1 = (const uint4*)biasT + (((h * 64 + i1) * 4 + t) * 2);
    uint4 wa0 = __ldg(bp0), wb0 = __ldg(bp0 + 1);
    uint4 wa1 = __ldg(bp1), wb1 = __ldg(bp1 + 1);
    const uint32_t bw0[8] = {wa0.x, wa0.y, wa0.z, wa0.w, wb0.x, wb0.y, wb0.z, wb0.w};
    const uint32_t bw1[8] = {wa1.x, wa1.y, wa1.z, wa1.w, wb1.x, wb1.y, wb1.z, wb1.w};

    float m0 = -1e30f, m1 = -1e30f;
#pragma unroll
    for (int nt = 0; nt < 7; nt++) {
        const float2 f0 = __half22float2(*(const __half2*)&bw0[nt]);
        const float2 f1 = __half22float2(*(const __half2*)&bw1[nt]);
        sc[nt][0] = fmaf(sc[nt][0], scale, f0.x);
        sc[nt][1] = fmaf(sc[nt][1], scale, f0.y);
        sc[nt][2] = fmaf(sc[nt][2], scale, f1.x);
        sc[nt][3] = fmaf(sc[nt][3], scale, f1.y);
        m0 = fmaxf(m0, fmaxf(sc[nt][0], sc[nt][1]));
        m1 = fmaxf(m1, fmaxf(sc[nt][2], sc[nt][3]));
    }
    m0 = fmaxf(m0, __shfl_xor_sync(0xffffffffu, m0, 1));
    m0 = fmaxf(m0, __shfl_xor_sync(0xffffffffu, m0, 2));
    m1 = fmaxf(m1, __shfl_xor_sync(0xffffffffu, m1, 1));
    m1 = fmaxf(m1, __shfl_xor_sync(0xffffffffu, m1, 2));

    float s0 = 0.f, s1 = 0.f;
#pragma unroll
    for (int nt = 0; nt < 7; nt++) {
        float p0 = __expf(sc[nt][0] - m0);
        float p1 = __expf(sc[nt][1] - m0);
        float p2 = __expf(sc[nt][2] - m1);
        float p3 = __expf(sc[nt][3] - m1);
        sc[nt][0] = p0; sc[nt][1] = p1; sc[nt][2] = p2; sc[nt][3] = p3;
        s0 += p0 + p1;
        s1 += p2 + p3;
    }
    s0 += __shfl_xor_sync(0xffffffffu, s0, 1);
    s0 += __shfl_xor_sync(0xffffffffu, s0, 2);
    s1 += __shfl_xor_sync(0xffffffffu, s1, 1);
    s1 += __shfl_xor_sync(0xffffffffu, s1, 2);
    const float inv0 = 1.f / s0, inv1 = 1.f / s1;

#pragma unroll
    for (int nt = 0; nt < 7; nt++) {
        sp[i0 * 36 + nt * 4 + t] = pack_h2(sc[nt][0], sc[nt][1]);
        sp[i1 * 36 + nt * 4 + t] = pack_h2(sc[nt][2], sc[nt][3]);
    }
    __syncwarp();

    float ov[4][4];
#pragma unroll
    for (int nt = 0; nt < 4; nt++)
#pragma unroll
        for (int r = 0; r < 4; r++) ov[nt][r] = 0.f;

#pragma unroll
    for (int ko = 0; ko < 4; ko++) {
        const uint32_t a0 = sp[(mtb + g) * 36 + ko * 8 + t];
        const uint32_t a1 = sp[(mtb + g + 8) * 36 + ko * 8 + t];
        const uint32_t a2 = sp[(mtb + g) * 36 + ko * 8 + 4 + t];
        const uint32_t a3 = sp[(mtb + g + 8) * 36 + ko * 8 + 4 + t];
#pragma unroll
        for (int nt = 0; nt < 4; nt++) {
            const uint32_t b0 = svT[(nt * 8 + g) * 36 + ko * 8 + t];
            const uint32_t b1 = svT[(nt * 8 + g) * 36 + ko * 8 + 4 + t];
            asm volatile(
                "mma.sync.aligned.m16n8k16.row.col.f32.f16.f16.f32 "
                "{%0,%1,%2,%3}, {%4,%5,%6,%7}, {%8,%9}, {%0,%1,%2,%3};"
                : "+f"(ov[nt][0]), "+f"(ov[nt][1]), "+f"(ov[nt][2]), "+f"(ov[nt][3])
                : "r"(a0), "r"(a1), "r"(a2), "r"(a3), "r"(b0), "r"(b1));
        }
    }

    const bool v0 = i0 < NTOK, v1 = i1 < NTOK;
#pragma unroll
    for (int nt = 0; nt < 4; nt++) {
        const int col = h * 32 + nt * 8 + 2 * t;
        if (v0) {
            *(__half2*)(out + ((size_t)b * NTOK + i0) * CDIM + col) =
                __floats2half2_rn(ov[nt][0] * inv0, ov[nt][1] * inv0);
        }
        if (v1) {
            *(__half2*)(out + ((size_t)b * NTOK + i1) * CDIM + col) =
                __floats2half2_rn(ov[nt][2] * inv1, ov[nt][3] * inv1);
        }
    }
}

// ---------------------------------------------------------------------------
// Launch
// ---------------------------------------------------------------------------
extern "C" void kernel_launch(void* const* d_in, const int* in_sizes, int n_in,
                              void* d_out, int out_size)
{
    const float* x      = (const float*)d_in[0];
    const float* qkv_w  = (const float*)d_in[1];
    const float* qkv_b  = (const float*)d_in[2];
    const float* rpb    = (const float*)d_in[3];
    const float* proj_w = (const float*)d_in[4];
    const float* proj_b = (const float*)d_in[5];
    float* out = (float*)d_out;

    __half* qkvh = nullptr;
    __half* atth = nullptr;
    uint32_t* wqkv = nullptr;
    uint32_t* wproj = nullptr;
    uint32_t* biasT = nullptr;
    cudaGetSymbolAddress((void**)&qkvh, g_qkv);
    cudaGetSymbolAddress((void**)&atth, g_att);
    cudaGetSymbolAddress((void**)&wqkv, g_wqkv);
    cudaGetSymbolAddress((void**)&wproj, g_wproj);
    cudaGetSymbolAddress((void**)&biasT, g_bias);

    constexpr int SMEM = 16384 * 4;   // 64 KB (A fragment image)
    cudaFuncSetAttribute(h16_gemm<float, __half, 768>,
                         cudaFuncAttributeMaxDynamicSharedMemorySize, SMEM);
    cudaFuncSetAttribute(h16_gemm<__half, float, 256>,
                         cudaFuncAttributeMaxDynamicSharedMemorySize, SMEM);

    // 0) one-time conversions (tiny)
    convert_w<<<384, 256>>>(qkv_w, wqkv, 768);
    convert_w<<<128, 256>>>(proj_w, wproj, 256);
    build_bias<<<64, 256>>>(rpb, biasT);

    // 1) QKV GEMM (barrier-free, fp16 out)
    h16_gemm<float, __half, 768><<<MROWS / 128, 128, SMEM>>>(x, wqkv, qkv_b, qkvh);

    // 2) Windowed attention
    {
        dim3 grid(BWIN, NHEAD);
        window_attn_h16<<<grid, 128>>>(qkvh, biasT, atth);
    }

    // 3) Projection GEMM (barrier-free, fp32 out)
    h16_gemm<__half, float, 256><<<MROWS / 128, 128, SMEM>>>(atth, wproj, proj_b, out);
}